// round 9
// baseline (speedup 1.0000x reference)
#include <cuda_runtime.h>
#include <cuda_fp16.h>
#include <cstdint>

// ---------------------------------------------------------------------------
// ChebyKAN: out[n,o] = clip( sum_{i,d=0..4} T_d(tanh(clip(x[n,i]))) * coeffs[o,i,d] )
// N=16384, I=2048, O=2048.  T0==1 folded into bias; GEMM K = I*4 = 8192, fp16.
// ldmatrix + mma.sync.m16n8k16 (compute_103 baseline ISA; tcgen05 unavailable).
// A features are generated IN the GEMM mainloop (registers -> swizzled STS),
// eliminating the 512 MB g_A DRAM round trip.  B flows via 3-stage TMA ring.
// ---------------------------------------------------------------------------

#define N_ROWS 16384
#define I_DIM  2048
#define O_DIM  2048
#define KDIM   8192
#define MT     128
#define NT     128
#define NPAIR  (KDIM / 64)           // 128 k-chunks of KC=64 (16 i per chunk)
#define NSTG   3
#define TILE_B 16384                 // 128 rows x 128 B (64 fp16)
#define STG_B  (2 * TILE_B)          // A (STS) + B (TMA)
#define SMEM_TOTAL (1024 + NSTG * STG_B)   // 99328
#define CLAMP10 10.0f

__device__ __align__(1024) unsigned char g_B[(size_t)O_DIM * KDIM * 2]; // 32 MB
__device__ float g_bias[O_DIM];

static __device__ __forceinline__ uint32_t swz128(uint32_t off) {
    return off ^ ((off >> 3) & 0x70);
}
static __device__ __forceinline__ float clampf(float v) {
    return fminf(fmaxf(v, -CLAMP10), CLAMP10);
}
static __device__ __forceinline__ uint32_t smem_u32(const void* p) {
    return (uint32_t)__cvta_generic_to_shared(p);
}
static __device__ __forceinline__ void mbar_init(uint32_t a, uint32_t cnt) {
    asm volatile("mbarrier.init.shared.b64 [%0], %1;" :: "r"(a), "r"(cnt) : "memory");
}
static __device__ __forceinline__ void mbar_expect_tx(uint32_t a, uint32_t bytes) {
    asm volatile("mbarrier.arrive.expect_tx.shared.b64 _, [%0], %1;" :: "r"(a), "r"(bytes) : "memory");
}
static __device__ __forceinline__ void mbar_wait(uint32_t a, uint32_t parity) {
    asm volatile(
        "{\n\t.reg .pred P;\n\t"
        "WL_%=:\n\t"
        "mbarrier.try_wait.parity.acquire.cta.shared::cta.b64 P, [%0], %1, 0x989680;\n\t"
        "@P bra.uni WD_%=;\n\t"
        "bra.uni WL_%=;\n\t"
        "WD_%=:\n\t}"
        :: "r"(a), "r"(parity) : "memory");
}
static __device__ __forceinline__ void bulk_g2s(uint32_t dst, const void* src,
                                                uint32_t bytes, uint32_t mbar) {
    asm volatile(
        "cp.async.bulk.shared::cluster.global.mbarrier::complete_tx::bytes [%0], [%1], %2, [%3];"
        :: "r"(dst), "l"(src), "r"(bytes), "r"(mbar) : "memory");
}
static __device__ __forceinline__ void ldsm_x4(uint32_t& r0, uint32_t& r1,
                                               uint32_t& r2, uint32_t& r3, uint32_t a) {
    asm volatile("ldmatrix.sync.aligned.m8n8.x4.shared.b16 {%0,%1,%2,%3}, [%4];"
                 : "=r"(r0), "=r"(r1), "=r"(r2), "=r"(r3) : "r"(a));
}
static __device__ __forceinline__ void mma16816(float* d, const uint32_t* a,
                                                uint32_t b0, uint32_t b1) {
    asm volatile(
        "mma.sync.aligned.m16n8k16.row.col.f32.f16.f16.f32 "
        "{%0,%1,%2,%3}, {%4,%5,%6,%7}, {%8,%9}, {%0,%1,%2,%3};"
        : "+f"(d[0]), "+f"(d[1]), "+f"(d[2]), "+f"(d[3])
        : "r"(a[0]), "r"(a[1]), "r"(a[2]), "r"(a[3]), "r"(b0), "r"(b1));
}
static __device__ __forceinline__ float tanh_fast(float v) {
    float r;
    asm("tanh.approx.f32 %0, %1;" : "=f"(r) : "f"(v));
    return r;
}

// features for 8 x-values -> 64 B into stage A region (4x STS.128, swizzled)
static __device__ __forceinline__ void gen_feat8(uint32_t stA, int row, int half,
                                                 const float4& xa, const float4& xb) {
    float vv[8] = {xa.x, xa.y, xa.z, xa.w, xb.x, xb.y, xb.z, xb.w};
    uint32_t u[16];
#pragma unroll
    for (int q = 0; q < 8; ++q) {
        float t  = tanh_fast(clampf(vv[q]));
        float t2 = 2.0f * t * t  - 1.0f;
        float t3 = 2.0f * t * t2 - t;
        float t4 = 2.0f * t * t3 - t2;
        __half2 p01 = __floats2half2_rn(t,  t2);
        __half2 p23 = __floats2half2_rn(t3, t4);
        u[q * 2 + 0] = *reinterpret_cast<uint32_t*>(&p01);
        u[q * 2 + 1] = *reinterpret_cast<uint32_t*>(&p23);
    }
    const uint32_t off0 = (uint32_t)row * 128u + (uint32_t)half * 64u;
#pragma unroll
    for (int p = 0; p < 4; ++p) {
        uint32_t dst = stA + swz128(off0 + p * 16);
        asm volatile("st.shared.v4.b32 [%0], {%1,%2,%3,%4};"
                     :: "r"(dst), "r"(u[p*4+0]), "r"(u[p*4+1]),
                        "r"(u[p*4+2]), "r"(u[p*4+3]) : "memory");
    }
}

// ---------------- prep: repack B (d=1..4 -> fp16 swizzled) + bias ------------
__global__ void prep_kernel(const float* __restrict__ coeffs) {
    const int o = blockIdx.x;
    float bsum = 0.0f;
    for (int t = 0; t < I_DIM / 256; ++t) {
        int i = t * 256 + threadIdx.x;
        const float* c5 = coeffs + ((size_t)o * I_DIM + i) * 5;
        float c0 = c5[0];
        __half2 p01 = __floats2half2_rn(c5[1], c5[2]);
        __half2 p23 = __floats2half2_rn(c5[3], c5[4]);
        uint2 u = make_uint2(*reinterpret_cast<uint32_t*>(&p01),
                             *reinterpret_cast<uint32_t*>(&p23));
        uint32_t off = (uint32_t)(o & 127) * 128u + (uint32_t)(i & 15) * 8u;
        size_t base  = ((size_t)((o >> 7) * NPAIR + (i >> 4))) << 14;
        *reinterpret_cast<uint2*>(g_B + base + swz128(off)) = u;
        bsum += c0;
    }
    __shared__ float red[256];
    red[threadIdx.x] = bsum;
    __syncthreads();
    for (int off = 128; off > 0; off >>= 1) {
        if (threadIdx.x < off) red[threadIdx.x] += red[threadIdx.x + off];
        __syncthreads();
    }
    if (threadIdx.x == 0) g_bias[o] = red[0];
}

// ---------------- GEMM: 128x128 CTA tile, 8 warps, fused A-feature gen -------
__global__ void __launch_bounds__(256, 2)
gemm_kernel(const float* __restrict__ x, float* __restrict__ C) {
    extern __shared__ __align__(1024) unsigned char smem[];
    const uint32_t sb = smem_u32(smem);
    const uint32_t stage0 = sb + 1024;

    const int tid  = threadIdx.x;
    const int wid  = tid >> 5, lane = tid & 31;
    const int wm   = wid & 3;
    const int wn   = wid >> 2;
    const int mtile = blockIdx.y, ntile = blockIdx.x;

    // feature-gen geometry: thread -> (row, half-of-16-i-block)
    const int frow  = tid >> 1;
    const int fhalf = tid & 1;
    const float* xRow = x + ((size_t)(mtile * MT + frow) * I_DIM) + fhalf * 8;

    if (tid == 0) {
#pragma unroll
        for (int s = 0; s < NSTG; ++s) mbar_init(sb + s * 8, 1);
    }
    __syncthreads();

    const unsigned char* bSrc = g_B + ((size_t)ntile * NPAIR << 14);

    // prologue: B TMA for stages 0..2; A features for chunks 0..2 via STS
    if (tid == 0) {
#pragma unroll
        for (int p = 0; p < NSTG; ++p) {
            uint32_t fb = sb + p * 8;
            mbar_expect_tx(fb, TILE_B);
            bulk_g2s(stage0 + p * STG_B + TILE_B, bSrc + ((size_t)p << 14), TILE_B, fb);
        }
    }
#pragma unroll
    for (int p = 0; p < NSTG; ++p) {
        const float4* xp = reinterpret_cast<const float4*>(xRow + p * 16);
        float4 xa = xp[0], xb = xp[1];
        gen_feat8(stage0 + p * STG_B, frow, fhalf, xa, xb);
    }
    __syncthreads();   // A(0..2) visible to all warps

    float acc[2][8][4];
#pragma unroll
    for (int mi = 0; mi < 2; ++mi)
#pragma unroll
        for (int ni = 0; ni < 8; ++ni)
#pragma unroll
            for (int r = 0; r < 4; ++r) acc[mi][ni][r] = 0.0f;

    const int g = lane >> 3, r8 = lane & 7;
    const uint32_t aRow = (uint32_t)(wm * 32 + ((g & 1) << 3) + r8);
    const uint32_t bRow = (uint32_t)(wn * 64 + ((g >> 1) << 3) + r8);
    const uint32_t aKb  = (uint32_t)((g >> 1) << 4);
    const uint32_t bKb  = (uint32_t)((g & 1) << 4);

    for (int k = 0; k < NPAIR; ++k) {
        const int sp = k % NSTG;
        const uint32_t fb = sb + sp * 8;
        const bool pf = (k + NSTG < NPAIR);

        // hoist x loads for chunk k+NSTG (latency hidden behind this chunk's mma)
        float4 xa, xb;
        if (pf) {
            const float4* xp = reinterpret_cast<const float4*>(xRow + (k + NSTG) * 16);
            xa = xp[0];
            xb = xp[1];
        }

        mbar_wait(fb, (uint32_t)((k / NSTG) & 1));   // B(k) ready; A(k) by earlier syncs

        const uint32_t stA = stage0 + sp * STG_B;
        const uint32_t stB = stA + TILE_B;

#pragma unroll
        for (int ks = 0; ks < 4; ++ks) {
            uint32_t a[2][4];
#pragma unroll
            for (int mi = 0; mi < 2; ++mi) {
                uint32_t off = (aRow + mi * 16) * 128u + (uint32_t)(ks * 32) + aKb;
                ldsm_x4(a[mi][0], a[mi][1], a[mi][2], a[mi][3], stA + swz128(off));
            }
            uint32_t b[4][4];
#pragma unroll
            for (int nj = 0; nj < 4; ++nj) {
                uint32_t off = (bRow + nj * 16) * 128u + (uint32_t)(ks * 32) + bKb;
                ldsm_x4(b[nj][0], b[nj][1], b[nj][2], b[nj][3], stB + swz128(off));
            }
#pragma unroll
            for (int mi = 0; mi < 2; ++mi)
#pragma unroll
                for (int ni = 0; ni < 8; ++ni)
                    mma16816(acc[mi][ni], a[mi],
                             b[ni >> 1][(ni & 1) * 2], b[ni >> 1][(ni & 1) * 2 + 1]);
        }

        __syncthreads();   // all warps done reading stage sp
        if (pf) {
            if (tid == 0) {
                mbar_expect_tx(fb, TILE_B);
                bulk_g2s(stA + TILE_B, bSrc + ((size_t)(k + NSTG) << 14), TILE_B, fb);
            }
            gen_feat8(stA, frow, fhalf, xa, xb);   // A(k+NSTG) -> freed stage
        }
    }

    // ---------------- epilogue: bias + clamp, float2 stores ------------------
    const int mBase = mtile * MT + wm * 32 + (lane >> 2);
    const int nBase = ntile * NT + wn * 64 + (lane & 3) * 2;

#pragma unroll
    for (int mi = 0; mi < 2; ++mi) {
#pragma unroll
        for (int ni = 0; ni < 8; ++ni) {
            const int n = nBase + ni * 8;
            const float b0 = g_bias[n], b1 = g_bias[n + 1];
            const int m0 = mBase + mi * 16;
            float2 v0, v1;
            v0.x = clampf(acc[mi][ni][0] + b0);
            v0.y = clampf(acc[mi][ni][1] + b1);
            v1.x = clampf(acc[mi][ni][2] + b0);
            v1.y = clampf(acc[mi][ni][3] + b1);
            *reinterpret_cast<float2*>(C + (size_t)m0 * O_DIM + n)       = v0;
            *reinterpret_cast<float2*>(C + (size_t)(m0 + 8) * O_DIM + n) = v1;
        }
    }
}

// ---------------------------------------------------------------------------
extern "C" void kernel_launch(void* const* d_in, const int* in_sizes, int n_in,
                              void* d_out, int out_size) {
    const float* x      = (const float*)d_in[0];
    const float* coeffs = (const float*)d_in[1];
    float* out          = (float*)d_out;

    cudaFuncSetAttribute(gemm_kernel, cudaFuncAttributeMaxDynamicSharedMemorySize, SMEM_TOTAL);

    prep_kernel<<<O_DIM, 256>>>(coeffs);
    gemm_kernel<<<dim3(O_DIM / NT, N_ROWS / MT), 256, SMEM_TOTAL>>>(x, out);
}

// round 11
// speedup vs baseline: 1.1621x; 1.1621x over previous
#include <cuda_runtime.h>
#include <cuda_fp16.h>
#include <cstdint>

// ---------------------------------------------------------------------------
// ChebyKAN: out[n,o] = clip( sum_{i,d=0..4} T_d(tanh(clip(x[n,i]))) * coeffs[o,i,d] )
// N=16384, I=2048, O=2048.  T0==1 folded into bias; GEMM K = I*4 = 8192, fp16.
// ldmatrix + mma.sync.m16n8k16 (compute_103 baseline ISA; tcgen05 unavailable).
// ONE fused grid: prepB blocks -> feat blocks -> gemm blocks, synchronized by
// device counters (producers have lower blockIdx; dispatch is bid-ordered).
// GEMM CTAs back-fill SMs while later feat blocks still run => prep overlapped.
// ---------------------------------------------------------------------------

#define N_ROWS 16384
#define I_DIM  2048
#define O_DIM  2048
#define KDIM   8192
#define MT     128
#define NT     128
#define NPAIR  (KDIM / 64)           // 128 k-chunks of KC=64
#define NSTG   3
#define TILE_B 16384                 // 128 rows x 128 B (64 fp16)
#define STG_B  (2 * TILE_B)
#define SMEM_TOTAL (1024 + NSTG * STG_B)   // 99328
#define NMT    (N_ROWS / MT)         // 128 m-tiles
#define PREPB_BLOCKS 2048            // one per o
#define FEAT_BLOCKS  32768           // 256 per mtile
#define GEMM_BLOCKS  2048
#define CLAMP10 10.0f

__device__ __align__(1024) unsigned char g_A[(size_t)N_ROWS * KDIM * 2]; // 256 MB
__device__ __align__(1024) unsigned char g_B[(size_t)O_DIM  * KDIM * 2]; //  32 MB
__device__ float g_bias[O_DIM];
__device__ unsigned g_cntB;          // prepB blocks done
__device__ unsigned g_cntM[NMT];     // feat blocks done per mtile

static __device__ __forceinline__ uint32_t swz128(uint32_t off) {
    return off ^ ((off >> 3) & 0x70);
}
static __device__ __forceinline__ float clampf(float v) {
    return fminf(fmaxf(v, -CLAMP10), CLAMP10);
}
static __device__ __forceinline__ uint32_t smem_u32(const void* p) {
    return (uint32_t)__cvta_generic_to_shared(p);
}
static __device__ __forceinline__ void mbar_init(uint32_t a, uint32_t cnt) {
    asm volatile("mbarrier.init.shared.b64 [%0], %1;" :: "r"(a), "r"(cnt) : "memory");
}
static __device__ __forceinline__ void mbar_expect_tx(uint32_t a, uint32_t bytes) {
    asm volatile("mbarrier.arrive.expect_tx.shared.b64 _, [%0], %1;" :: "r"(a), "r"(bytes) : "memory");
}
static __device__ __forceinline__ void mbar_wait(uint32_t a, uint32_t parity) {
    asm volatile(
        "{\n\t.reg .pred P;\n\t"
        "WL_%=:\n\t"
        "mbarrier.try_wait.parity.acquire.cta.shared::cta.b64 P, [%0], %1, 0x989680;\n\t"
        "@P bra.uni WD_%=;\n\t"
        "bra.uni WL_%=;\n\t"
        "WD_%=:\n\t}"
        :: "r"(a), "r"(parity) : "memory");
}
static __device__ __forceinline__ void bulk_g2s(uint32_t dst, const void* src,
                                                uint32_t bytes, uint32_t mbar) {
    asm volatile(
        "cp.async.bulk.shared::cluster.global.mbarrier::complete_tx::bytes [%0], [%1], %2, [%3];"
        :: "r"(dst), "l"(src), "r"(bytes), "r"(mbar) : "memory");
}
static __device__ __forceinline__ void ldsm_x4(uint32_t& r0, uint32_t& r1,
                                               uint32_t& r2, uint32_t& r3, uint32_t a) {
    asm volatile("ldmatrix.sync.aligned.m8n8.x4.shared.b16 {%0,%1,%2,%3}, [%4];"
                 : "=r"(r0), "=r"(r1), "=r"(r2), "=r"(r3) : "r"(a));
}
static __device__ __forceinline__ void mma16816(float* d, const uint32_t* a,
                                                uint32_t b0, uint32_t b1) {
    asm volatile(
        "mma.sync.aligned.m16n8k16.row.col.f32.f16.f16.f32 "
        "{%0,%1,%2,%3}, {%4,%5,%6,%7}, {%8,%9}, {%0,%1,%2,%3};"
        : "+f"(d[0]), "+f"(d[1]), "+f"(d[2]), "+f"(d[3])
        : "r"(a[0]), "r"(a[1]), "r"(a[2]), "r"(a[3]), "r"(b0), "r"(b1));
}
static __device__ __forceinline__ float tanh_fast(float v) {
    float r;
    asm("tanh.approx.f32 %0, %1;" : "=f"(r) : "f"(v));
    return r;
}
static __device__ __forceinline__ unsigned ld_acq(const unsigned* p) {
    unsigned v;
    asm volatile("ld.acquire.gpu.global.u32 %0, [%1];" : "=r"(v) : "l"(p));
    return v;
}

// ---------------- init: zero counters (each graph replay) --------------------
__global__ void init_kernel() {
    if (threadIdx.x < NMT) g_cntM[threadIdx.x] = 0;
    if (threadIdx.x == 0)  g_cntB = 0;
}

// ---------------- fused mega-kernel ------------------------------------------
__global__ void __launch_bounds__(256, 2)
fused_kernel(const float* __restrict__ x, const float* __restrict__ coeffs,
             float* __restrict__ C) {
    const int bid = blockIdx.x;
    const int tid = threadIdx.x;

    if (bid < PREPB_BLOCKS) {
        // ---- repack B (d=1..4 -> fp16 swizzled) + bias for output o=bid ----
        const int o = bid;
        float bsum = 0.0f;
        for (int t = 0; t < I_DIM / 256; ++t) {
            int i = t * 256 + tid;
            const float* c5 = coeffs + ((size_t)o * I_DIM + i) * 5;
            float c0 = c5[0];
            __half2 p01 = __floats2half2_rn(c5[1], c5[2]);
            __half2 p23 = __floats2half2_rn(c5[3], c5[4]);
            uint2 u = make_uint2(*reinterpret_cast<uint32_t*>(&p01),
                                 *reinterpret_cast<uint32_t*>(&p23));
            uint32_t off = (uint32_t)(o & 127) * 128u + (uint32_t)(i & 15) * 8u;
            size_t base  = ((size_t)((o >> 7) * NPAIR + (i >> 4))) << 14;
            *reinterpret_cast<uint2*>(g_B + base + swz128(off)) = u;
            bsum += c0;
        }
        __shared__ float red[256];
        red[tid] = bsum;
        __syncthreads();
        for (int off = 128; off > 0; off >>= 1) {
            if (tid < off) red[tid] += red[tid + off];
            __syncthreads();
        }
        if (tid == 0) g_bias[o] = red[0];
        __threadfence();
        __syncthreads();
        if (tid == 0) atomicAdd(&g_cntB, 1u);
        return;
    }

    if (bid < PREPB_BLOCKS + FEAT_BLOCKS) {
        // ---- feature map: 256 blocks per mtile, mtile ascending with bid ----
        const int fid   = bid - PREPB_BLOCKS;
        const int mtile = fid >> 8;              // 256 blocks per mtile
        const int idx4l = (fid & 255) * 256 + tid;   // [0, 65536) within mtile
        const int n = mtile * MT + (idx4l >> 9);     // 512 idx4 per row
        const int j = idx4l & 511;
        float4 xv = reinterpret_cast<const float4*>(x)[(size_t)n * (I_DIM / 4) + j];
        float vv[4] = {xv.x, xv.y, xv.z, xv.w};
        uint32_t u[8];
#pragma unroll
        for (int q = 0; q < 4; ++q) {
            float t  = tanh_fast(clampf(vv[q]));
            float t2 = 2.0f * t * t  - 1.0f;
            float t3 = 2.0f * t * t2 - t;
            float t4 = 2.0f * t * t3 - t2;
            __half2 p01 = __floats2half2_rn(t,  t2);
            __half2 p23 = __floats2half2_rn(t3, t4);
            u[q * 2 + 0] = *reinterpret_cast<uint32_t*>(&p01);
            u[q * 2 + 1] = *reinterpret_cast<uint32_t*>(&p23);
        }
        const int i0 = j * 4;
        const uint32_t off0 = (uint32_t)(n & 127) * 128u + (uint32_t)(i0 & 15) * 8u;
        const size_t  base  = ((size_t)((n >> 7) * NPAIR + (i0 >> 4))) << 14;
        *reinterpret_cast<uint4*>(g_A + base + swz128(off0)) =
            make_uint4(u[0], u[1], u[2], u[3]);
        *reinterpret_cast<uint4*>(g_A + base + swz128(off0 + 16)) =
            make_uint4(u[4], u[5], u[6], u[7]);
        __threadfence();
        __syncthreads();
        if (tid == 0) atomicAdd(&g_cntM[mtile], 1u);
        return;
    }

    // ---- GEMM: 128x128 CTA tile, 8 warps (4m x 2n), mma.sync ---------------
    extern __shared__ __align__(1024) unsigned char smem[];
    const uint32_t sb = smem_u32(smem);
    const uint32_t stage0 = sb + 1024;

    const int gid  = bid - (PREPB_BLOCKS + FEAT_BLOCKS);
    const int wid  = tid >> 5, lane = tid & 31;
    const int wm   = wid & 3;
    const int wn   = wid >> 2;
    const int mtile = gid >> 4;          // ascending: matches feat completion
    const int ntile = gid & 15;

    if (tid == 0) {
#pragma unroll
        for (int s = 0; s < NSTG; ++s) mbar_init(sb + s * 8, 1);
        // wait for producers: all prepB blocks + this mtile's 256 feat blocks
        while (ld_acq(&g_cntB) < PREPB_BLOCKS)        __nanosleep(64);
        while (ld_acq(&g_cntM[mtile]) < 256u)         __nanosleep(64);
    }
    __syncthreads();

    const unsigned char* aSrc = g_A + ((size_t)mtile * NPAIR << 14);
    const unsigned char* bSrc = g_B + ((size_t)ntile * NPAIR << 14);

    if (tid == 0) {
#pragma unroll
        for (int p = 0; p < NSTG; ++p) {
            uint32_t fb = sb + p * 8;
            uint32_t dst = stage0 + p * STG_B;
            mbar_expect_tx(fb, STG_B);
            bulk_g2s(dst,          aSrc + ((size_t)p << 14), TILE_B, fb);
            bulk_g2s(dst + TILE_B, bSrc + ((size_t)p << 14), TILE_B, fb);
        }
    }

    float acc[2][8][4];
#pragma unroll
    for (int mi = 0; mi < 2; ++mi)
#pragma unroll
        for (int ni = 0; ni < 8; ++ni)
#pragma unroll
            for (int r = 0; r < 4; ++r) acc[mi][ni][r] = 0.0f;

    const int g = lane >> 3, r8 = lane & 7;
    const uint32_t aRow = (uint32_t)(wm * 32 + ((g & 1) << 3) + r8);
    const uint32_t bRow = (uint32_t)(wn * 64 + ((g >> 1) << 3) + r8);
    const uint32_t aKb  = (uint32_t)((g >> 1) << 4);
    const uint32_t bKb  = (uint32_t)((g & 1) << 4);

    for (int k = 0; k < NPAIR; ++k) {
        const int sp = k % NSTG;
        const uint32_t fb = sb + sp * 8;
        mbar_wait(fb, (uint32_t)((k / NSTG) & 1));

        const uint32_t stA = stage0 + sp * STG_B;
        const uint32_t stB = stA + TILE_B;

#pragma unroll
        for (int ks = 0; ks < 4; ++ks) {
            uint32_t a[2][4];
#pragma unroll
            for (int mi = 0; mi < 2; ++mi) {
                uint32_t off = (aRow + mi * 16) * 128u + (uint32_t)(ks * 32) + aKb;
                ldsm_x4(a[mi][0], a[mi][1], a[mi][2], a[mi][3], stA + swz128(off));
            }
            uint32_t b[4][4];
#pragma unroll
            for (int nj = 0; nj < 4; ++nj) {
                uint32_t off = (bRow + nj * 16) * 128u + (uint32_t)(ks * 32) + bKb;
                ldsm_x4(b[nj][0], b[nj][1], b[nj][2], b[nj][3], stB + swz128(off));
            }
#pragma unroll
            for (int mi = 0; mi < 2; ++mi)
#pragma unroll
                for (int ni = 0; ni < 8; ++ni)
                    mma16816(acc[mi][ni], a[mi],
                             b[ni >> 1][(ni & 1) * 2], b[ni >> 1][(ni & 1) * 2 + 1]);
        }

        __syncthreads();   // all warps done reading stage sp
        if (tid == 0 && k + NSTG < NPAIR) {
            const int kn = k + NSTG;
            uint32_t dst = stage0 + sp * STG_B;
            mbar_expect_tx(fb, STG_B);
            bulk_g2s(dst,          aSrc + ((size_t)kn << 14), TILE_B, fb);
            bulk_g2s(dst + TILE_B, bSrc + ((size_t)kn << 14), TILE_B, fb);
        }
    }

    // ---------------- epilogue: bias + clamp, float2 stores ------------------
    const int mBase = mtile * MT + wm * 32 + (lane >> 2);
    const int nBase = ntile * NT + wn * 64 + (lane & 3) * 2;

#pragma unroll
    for (int mi = 0; mi < 2; ++mi) {
#pragma unroll
        for (int ni = 0; ni < 8; ++ni) {
            const int n = nBase + ni * 8;
            const float b0 = g_bias[n], b1 = g_bias[n + 1];
            const int m0 = mBase + mi * 16;
            float2 v0, v1;
            v0.x = clampf(acc[mi][ni][0] + b0);
            v0.y = clampf(acc[mi][ni][1] + b1);
            v1.x = clampf(acc[mi][ni][2] + b0);
            v1.y = clampf(acc[mi][ni][3] + b1);
            *reinterpret_cast<float2*>(C + (size_t)m0 * O_DIM + n)       = v0;
            *reinterpret_cast<float2*>(C + (size_t)(m0 + 8) * O_DIM + n) = v1;
        }
    }
}

// ---------------------------------------------------------------------------
extern "C" void kernel_launch(void* const* d_in, const int* in_sizes, int n_in,
                              void* d_out, int out_size) {
    const float* x      = (const float*)d_in[0];
    const float* coeffs = (const float*)d_in[1];
    float* out          = (float*)d_out;

    cudaFuncSetAttribute(fused_kernel,
                         cudaFuncAttributeMaxDynamicSharedMemorySize, SMEM_TOTAL);

    init_kernel <<<1, 128>>>();
    fused_kernel<<<PREPB_BLOCKS + FEAT_BLOCKS + GEMM_BLOCKS, 256, SMEM_TOTAL>>>(
        x, coeffs, out);
}

// round 12
// speedup vs baseline: 1.2693x; 1.0923x over previous
#include <cuda_runtime.h>
#include <cuda_fp16.h>
#include <cstdint>

// ---------------------------------------------------------------------------
// ChebyKAN: out[n,o] = clip( sum_{i,d=0..4} T_d(tanh(clip(x[n,i]))) * coeffs[o,i,d] )
// N=16384, I=2048, O=2048.  T0==1 folded into bias; GEMM K = I*4 = 8192, fp16.
// ldmatrix + mma.sync.m16n8k16 (compute_103 baseline ISA; tcgen05 unavailable).
// ONE fused grid: prepB -> feat (ILP-8, 32 blocks/mtile) -> gemm, ordered by
// blockIdx and gated by device counters.  GEMM CTAs back-fill SMs while later
// feat blocks still run, hiding the prep phase behind the GEMM.
// ---------------------------------------------------------------------------

#define N_ROWS 16384
#define I_DIM  2048
#define O_DIM  2048
#define KDIM   8192
#define MT     128
#define NT     128
#define NPAIR  (KDIM / 64)           // 128 k-chunks of KC=64
#define NSTG   3
#define TILE_B 16384                 // 128 rows x 128 B (64 fp16)
#define STG_B  (2 * TILE_B)
#define SMEM_TOTAL (1024 + NSTG * STG_B)   // 99328
#define NMT    (N_ROWS / MT)         // 128 m-tiles
#define PREPB_BLOCKS 2048            // one per o
#define FEAT_PER_MT  32              // feat blocks per mtile (ILP-8 each)
#define FEAT_BLOCKS  (NMT * FEAT_PER_MT)   // 4096
#define GEMM_BLOCKS  2048
#define CLAMP10 10.0f

__device__ __align__(1024) unsigned char g_A[(size_t)N_ROWS * KDIM * 2]; // 256 MB
__device__ __align__(1024) unsigned char g_B[(size_t)O_DIM  * KDIM * 2]; //  32 MB
__device__ float g_bias[O_DIM];
__device__ unsigned g_cntB;          // prepB blocks done
__device__ unsigned g_cntM[NMT];     // feat blocks done per mtile

static __device__ __forceinline__ uint32_t swz128(uint32_t off) {
    return off ^ ((off >> 3) & 0x70);
}
static __device__ __forceinline__ float clampf(float v) {
    return fminf(fmaxf(v, -CLAMP10), CLAMP10);
}
static __device__ __forceinline__ uint32_t smem_u32(const void* p) {
    return (uint32_t)__cvta_generic_to_shared(p);
}
static __device__ __forceinline__ void mbar_init(uint32_t a, uint32_t cnt) {
    asm volatile("mbarrier.init.shared.b64 [%0], %1;" :: "r"(a), "r"(cnt) : "memory");
}
static __device__ __forceinline__ void mbar_expect_tx(uint32_t a, uint32_t bytes) {
    asm volatile("mbarrier.arrive.expect_tx.shared.b64 _, [%0], %1;" :: "r"(a), "r"(bytes) : "memory");
}
static __device__ __forceinline__ void mbar_wait(uint32_t a, uint32_t parity) {
    asm volatile(
        "{\n\t.reg .pred P;\n\t"
        "WL_%=:\n\t"
        "mbarrier.try_wait.parity.acquire.cta.shared::cta.b64 P, [%0], %1, 0x989680;\n\t"
        "@P bra.uni WD_%=;\n\t"
        "bra.uni WL_%=;\n\t"
        "WD_%=:\n\t}"
        :: "r"(a), "r"(parity) : "memory");
}
static __device__ __forceinline__ void bulk_g2s(uint32_t dst, const void* src,
                                                uint32_t bytes, uint32_t mbar) {
    asm volatile(
        "cp.async.bulk.shared::cluster.global.mbarrier::complete_tx::bytes [%0], [%1], %2, [%3];"
        :: "r"(dst), "l"(src), "r"(bytes), "r"(mbar) : "memory");
}
static __device__ __forceinline__ void ldsm_x4(uint32_t& r0, uint32_t& r1,
                                               uint32_t& r2, uint32_t& r3, uint32_t a) {
    asm volatile("ldmatrix.sync.aligned.m8n8.x4.shared.b16 {%0,%1,%2,%3}, [%4];"
                 : "=r"(r0), "=r"(r1), "=r"(r2), "=r"(r3) : "r"(a));
}
static __device__ __forceinline__ void mma16816(float* d, const uint32_t* a,
                                                uint32_t b0, uint32_t b1) {
    asm volatile(
        "mma.sync.aligned.m16n8k16.row.col.f32.f16.f16.f32 "
        "{%0,%1,%2,%3}, {%4,%5,%6,%7}, {%8,%9}, {%0,%1,%2,%3};"
        : "+f"(d[0]), "+f"(d[1]), "+f"(d[2]), "+f"(d[3])
        : "r"(a[0]), "r"(a[1]), "r"(a[2]), "r"(a[3]), "r"(b0), "r"(b1));
}
static __device__ __forceinline__ float tanh_fast(float v) {
    float r;
    asm("tanh.approx.f32 %0, %1;" : "=f"(r) : "f"(v));
    return r;
}
static __device__ __forceinline__ unsigned ld_acq(const unsigned* p) {
    unsigned v;
    asm volatile("ld.acquire.gpu.global.u32 %0, [%1];" : "=r"(v) : "l"(p));
    return v;
}

// ---------------- init: zero counters (each graph replay) --------------------
__global__ void init_kernel() {
    if (threadIdx.x < NMT) g_cntM[threadIdx.x] = 0;
    if (threadIdx.x == 0)  g_cntB = 0;
}

// ---------------- fused mega-kernel ------------------------------------------
__global__ void __launch_bounds__(256, 2)
fused_kernel(const float* __restrict__ x, const float* __restrict__ coeffs,
             float* __restrict__ C) {
    const int bid = blockIdx.x;
    const int tid = threadIdx.x;

    if (bid < PREPB_BLOCKS) {
        // ---- repack B (d=1..4 -> fp16 swizzled) + bias for output o=bid ----
        const int o = bid;
        float bsum = 0.0f;
#pragma unroll
        for (int t = 0; t < I_DIM / 256; ++t) {
            int i = t * 256 + tid;
            const float* c5 = coeffs + ((size_t)o * I_DIM + i) * 5;
            float c0 = c5[0];
            __half2 p01 = __floats2half2_rn(c5[1], c5[2]);
            __half2 p23 = __floats2half2_rn(c5[3], c5[4]);
            uint2 u = make_uint2(*reinterpret_cast<uint32_t*>(&p01),
                                 *reinterpret_cast<uint32_t*>(&p23));
            uint32_t off = (uint32_t)(o & 127) * 128u + (uint32_t)(i & 15) * 8u;
            size_t base  = ((size_t)((o >> 7) * NPAIR + (i >> 4))) << 14;
            *reinterpret_cast<uint2*>(g_B + base + swz128(off)) = u;
            bsum += c0;
        }
        __shared__ float red[256];
        red[tid] = bsum;
        __syncthreads();
        for (int off = 128; off > 0; off >>= 1) {
            if (tid < off) red[tid] += red[tid + off];
            __syncthreads();
        }
        if (tid == 0) g_bias[o] = red[0];
        __threadfence();
        __syncthreads();
        if (tid == 0) atomicAdd(&g_cntB, 1u);
        return;
    }

    if (bid < PREPB_BLOCKS + FEAT_BLOCKS) {
        // ---- feature map: 32 blocks per mtile, 8 float4/thread (MLP=8) -----
        const int fid   = bid - PREPB_BLOCKS;
        const int mtile = fid / FEAT_PER_MT;          // ascending with bid
        const int fl    = fid % FEAT_PER_MT;
        // mtile slab = 65536 float4; this block covers 2048 of them.
        const int base4 = mtile * (MT * I_DIM / 4) + fl * 2048;

        float4 xv[8];
#pragma unroll
        for (int r = 0; r < 8; ++r)
            xv[r] = reinterpret_cast<const float4*>(x)[(size_t)base4 + r * 256 + tid];

#pragma unroll
        for (int r = 0; r < 8; ++r) {
            const int idx4 = base4 + r * 256 + tid;
            const int n = idx4 >> 9;
            const int j = idx4 & 511;
            float vv[4] = {xv[r].x, xv[r].y, xv[r].z, xv[r].w};
            uint32_t u[8];
#pragma unroll
            for (int q = 0; q < 4; ++q) {
                float t  = tanh_fast(clampf(vv[q]));
                float t2 = 2.0f * t * t  - 1.0f;
                float t3 = 2.0f * t * t2 - t;
                float t4 = 2.0f * t * t3 - t2;
                __half2 p01 = __floats2half2_rn(t,  t2);
                __half2 p23 = __floats2half2_rn(t3, t4);
                u[q * 2 + 0] = *reinterpret_cast<uint32_t*>(&p01);
                u[q * 2 + 1] = *reinterpret_cast<uint32_t*>(&p23);
            }
            const int i0 = j * 4;
            const uint32_t off0 = (uint32_t)(n & 127) * 128u + (uint32_t)(i0 & 15) * 8u;
            const size_t  base  = ((size_t)((n >> 7) * NPAIR + (i0 >> 4))) << 14;
            *reinterpret_cast<uint4*>(g_A + base + swz128(off0)) =
                make_uint4(u[0], u[1], u[2], u[3]);
            *reinterpret_cast<uint4*>(g_A + base + swz128(off0 + 16)) =
                make_uint4(u[4], u[5], u[6], u[7]);
        }
        __threadfence();
        __syncthreads();
        if (tid == 0) atomicAdd(&g_cntM[mtile], 1u);
        return;
    }

    // ---- GEMM: 128x128 CTA tile, 8 warps (4m x 2n), mma.sync (R8 body) -----
    extern __shared__ __align__(1024) unsigned char smem[];
    const uint32_t sb = smem_u32(smem);
    const uint32_t stage0 = sb + 1024;

    const int gid  = bid - (PREPB_BLOCKS + FEAT_BLOCKS);
    const int wid  = tid >> 5, lane = tid & 31;
    const int wm   = wid & 3;
    const int wn   = wid >> 2;
    const int mtile = gid >> 4;          // ascending: matches feat completion
    const int ntile = gid & 15;

    if (tid == 0) {
#pragma unroll
        for (int s = 0; s < NSTG; ++s) mbar_init(sb + s * 8, 1);
        // wait for producers: all prepB blocks + this mtile's feat blocks
        while (ld_acq(&g_cntB) < PREPB_BLOCKS)             __nanosleep(64);
        while (ld_acq(&g_cntM[mtile]) < (unsigned)FEAT_PER_MT) __nanosleep(64);
    }
    __syncthreads();

    const unsigned char* aSrc = g_A + ((size_t)mtile * NPAIR << 14);
    const unsigned char* bSrc = g_B + ((size_t)ntile * NPAIR << 14);

    if (tid == 0) {
#pragma unroll
        for (int p = 0; p < NSTG; ++p) {
            uint32_t fb = sb + p * 8;
            uint32_t dst = stage0 + p * STG_B;
            mbar_expect_tx(fb, STG_B);
            bulk_g2s(dst,          aSrc + ((size_t)p << 14), TILE_B, fb);
            bulk_g2s(dst + TILE_B, bSrc + ((size_t)p << 14), TILE_B, fb);
        }
    }

    float acc[2][8][4];
#pragma unroll
    for (int mi = 0; mi < 2; ++mi)
#pragma unroll
        for (int ni = 0; ni < 8; ++ni)
#pragma unroll
            for (int r = 0; r < 4; ++r) acc[mi][ni][r] = 0.0f;

    const int g = lane >> 3, r8 = lane & 7;
    const uint32_t aRow = (uint32_t)(wm * 32 + ((g & 1) << 3) + r8);
    const uint32_t bRow = (uint32_t)(wn * 64 + ((g >> 1) << 3) + r8);
    const uint32_t aKb  = (uint32_t)((g >> 1) << 4);
    const uint32_t bKb  = (uint32_t)((g & 1) << 4);

    for (int k = 0; k < NPAIR; ++k) {
        const int sp = k % NSTG;
        const uint32_t fb = sb + sp * 8;
        mbar_wait(fb, (uint32_t)((k / NSTG) & 1));

        const uint32_t stA = stage0 + sp * STG_B;
        const uint32_t stB = stA + TILE_B;

#pragma unroll
        for (int ks = 0; ks < 4; ++ks) {
            uint32_t a[2][4];
#pragma unroll
            for (int mi = 0; mi < 2; ++mi) {
                uint32_t off = (aRow + mi * 16) * 128u + (uint32_t)(ks * 32) + aKb;
                ldsm_x4(a[mi][0], a[mi][1], a[mi][2], a[mi][3], stA + swz128(off));
            }
            uint32_t b[4][4];
#pragma unroll
            for (int nj = 0; nj < 4; ++nj) {
                uint32_t off = (bRow + nj * 16) * 128u + (uint32_t)(ks * 32) + bKb;
                ldsm_x4(b[nj][0], b[nj][1], b[nj][2], b[nj][3], stB + swz128(off));
            }
#pragma unroll
            for (int mi = 0; mi < 2; ++mi)
#pragma unroll
                for (int ni = 0; ni < 8; ++ni)
                    mma16816(acc[mi][ni], a[mi],
                             b[ni >> 1][(ni & 1) * 2], b[ni >> 1][(ni & 1) * 2 + 1]);
        }

        __syncthreads();   // all warps done reading stage sp
        if (tid == 0 && k + NSTG < NPAIR) {
            const int kn = k + NSTG;
            uint32_t dst = stage0 + sp * STG_B;
            mbar_expect_tx(fb, STG_B);
            bulk_g2s(dst,          aSrc + ((size_t)kn << 14), TILE_B, fb);
            bulk_g2s(dst + TILE_B, bSrc + ((size_t)kn << 14), TILE_B, fb);
        }
    }

    // ---------------- epilogue: bias + clamp, float2 stores ------------------
    const int mBase = mtile * MT + wm * 32 + (lane >> 2);
    const int nBase = ntile * NT + wn * 64 + (lane & 3) * 2;

#pragma unroll
    for (int mi = 0; mi < 2; ++mi) {
#pragma unroll
        for (int ni = 0; ni < 8; ++ni) {
            const int n = nBase + ni * 8;
            const float b0 = g_bias[n], b1 = g_bias[n + 1];
            const int m0 = mBase + mi * 16;
            float2 v0, v1;
            v0.x = clampf(acc[mi][ni][0] + b0);
            v0.y = clampf(acc[mi][ni][1] + b1);
            v1.x = clampf(acc[mi][ni][2] + b0);
            v1.y = clampf(acc[mi][ni][3] + b1);
            *reinterpret_cast<float2*>(C + (size_t)m0 * O_DIM + n)       = v0;
            *reinterpret_cast<float2*>(C + (size_t)(m0 + 8) * O_DIM + n) = v1;
        }
    }
}

// ---------------------------------------------------------------------------
extern "C" void kernel_launch(void* const* d_in, const int* in_sizes, int n_in,
                              void* d_out, int out_size) {
    const float* x      = (const float*)d_in[0];
    const float* coeffs = (const float*)d_in[1];
    float* out          = (float*)d_out;

    cudaFuncSetAttribute(fused_kernel,
                         cudaFuncAttributeMaxDynamicSharedMemorySize, SMEM_TOTAL);

    init_kernel <<<1, 128>>>();
    fused_kernel<<<PREPB_BLOCKS + FEAT_BLOCKS + GEMM_BLOCKS, 256, SMEM_TOTAL>>>(
        x, coeffs, out);
}

// round 13
// speedup vs baseline: 1.3062x; 1.0290x over previous
#include <cuda_runtime.h>
#include <cuda_fp16.h>
#include <cstdint>

// ---------------------------------------------------------------------------
// ChebyKAN: out[n,o] = clip( sum_{i,d=0..4} T_d(tanh(clip(x[n,i]))) * coeffs[o,i,d] )
// N=16384, I=2048, O=2048.  T0==1 folded into bias; GEMM K = I*4 = 8192, fp16.
// ldmatrix + mma.sync.m16n8k16 (compute_103 baseline ISA; tcgen05 unavailable).
// R8 GEMM (3-stage bulk-async ring + per-chunk __syncthreads — measured optimum
// across 5 mainloop variants).  feat: 2 independent float4/thread (MLP x2).
// Serial prep -> GEMM (overlap via SM-mixing measured net-negative: R9/R11/R12).
// ---------------------------------------------------------------------------

#define N_ROWS 16384
#define I_DIM  2048
#define O_DIM  2048
#define KDIM   8192
#define MT     128
#define NT     128
#define NPAIR  (KDIM / 64)           // 128 k-chunks of KC=64
#define NSTG   3
#define TILE_B 16384                 // 128 rows x 128 B (64 fp16)
#define STG_B  (2 * TILE_B)
#define SMEM_TOTAL (1024 + NSTG * STG_B)   // 99328
#define FEAT_BLOCKS (N_ROWS * I_DIM / 8 / 256)   // 16384 (2 float4 per thread)
#define CLAMP10 10.0f

__device__ __align__(1024) unsigned char g_A[(size_t)N_ROWS * KDIM * 2]; // 256 MB
__device__ __align__(1024) unsigned char g_B[(size_t)O_DIM  * KDIM * 2]; //  32 MB
__device__ float g_bias[O_DIM];

static __device__ __forceinline__ uint32_t swz128(uint32_t off) {
    return off ^ ((off >> 3) & 0x70);
}
static __device__ __forceinline__ float clampf(float v) {
    return fminf(fmaxf(v, -CLAMP10), CLAMP10);
}
static __device__ __forceinline__ uint32_t smem_u32(const void* p) {
    return (uint32_t)__cvta_generic_to_shared(p);
}
static __device__ __forceinline__ void mbar_init(uint32_t a, uint32_t cnt) {
    asm volatile("mbarrier.init.shared.b64 [%0], %1;" :: "r"(a), "r"(cnt) : "memory");
}
static __device__ __forceinline__ void mbar_expect_tx(uint32_t a, uint32_t bytes) {
    asm volatile("mbarrier.arrive.expect_tx.shared.b64 _, [%0], %1;" :: "r"(a), "r"(bytes) : "memory");
}
static __device__ __forceinline__ void mbar_wait(uint32_t a, uint32_t parity) {
    asm volatile(
        "{\n\t.reg .pred P;\n\t"
        "WL_%=:\n\t"
        "mbarrier.try_wait.parity.acquire.cta.shared::cta.b64 P, [%0], %1, 0x989680;\n\t"
        "@P bra.uni WD_%=;\n\t"
        "bra.uni WL_%=;\n\t"
        "WD_%=:\n\t}"
        :: "r"(a), "r"(parity) : "memory");
}
static __device__ __forceinline__ void bulk_g2s(uint32_t dst, const void* src,
                                                uint32_t bytes, uint32_t mbar) {
    asm volatile(
        "cp.async.bulk.shared::cluster.global.mbarrier::complete_tx::bytes [%0], [%1], %2, [%3];"
        :: "r"(dst), "l"(src), "r"(bytes), "r"(mbar) : "memory");
}
static __device__ __forceinline__ void ldsm_x4(uint32_t& r0, uint32_t& r1,
                                               uint32_t& r2, uint32_t& r3, uint32_t a) {
    asm volatile("ldmatrix.sync.aligned.m8n8.x4.shared.b16 {%0,%1,%2,%3}, [%4];"
                 : "=r"(r0), "=r"(r1), "=r"(r2), "=r"(r3) : "r"(a));
}
static __device__ __forceinline__ void mma16816(float* d, const uint32_t* a,
                                                uint32_t b0, uint32_t b1) {
    asm volatile(
        "mma.sync.aligned.m16n8k16.row.col.f32.f16.f16.f32 "
        "{%0,%1,%2,%3}, {%4,%5,%6,%7}, {%8,%9}, {%0,%1,%2,%3};"
        : "+f"(d[0]), "+f"(d[1]), "+f"(d[2]), "+f"(d[3])
        : "r"(a[0]), "r"(a[1]), "r"(a[2]), "r"(a[3]), "r"(b0), "r"(b1));
}
static __device__ __forceinline__ float tanh_fast(float v) {
    float r;
    asm("tanh.approx.f32 %0, %1;" : "=f"(r) : "f"(v));
    return r;
}

// convert one float4 of x (row n, float4-index j) and store 32B into g_A
static __device__ __forceinline__ void feat_store4(int n, int j, const float4& xv) {
    float vv[4] = {xv.x, xv.y, xv.z, xv.w};
    uint32_t u[8];
#pragma unroll
    for (int q = 0; q < 4; ++q) {
        float t  = tanh_fast(clampf(vv[q]));
        float t2 = 2.0f * t * t  - 1.0f;
        float t3 = 2.0f * t * t2 - t;
        float t4 = 2.0f * t * t3 - t2;
        __half2 p01 = __floats2half2_rn(t,  t2);
        __half2 p23 = __floats2half2_rn(t3, t4);
        u[q * 2 + 0] = *reinterpret_cast<uint32_t*>(&p01);
        u[q * 2 + 1] = *reinterpret_cast<uint32_t*>(&p23);
    }
    const int i0 = j * 4;
    const uint32_t off0 = (uint32_t)(n & 127) * 128u + (uint32_t)(i0 & 15) * 8u;
    const size_t  base  = ((size_t)((n >> 7) * NPAIR + (i0 >> 4))) << 14;
    *reinterpret_cast<uint4*>(g_A + base + swz128(off0)) =
        make_uint4(u[0], u[1], u[2], u[3]);
    *reinterpret_cast<uint4*>(g_A + base + swz128(off0 + 16)) =
        make_uint4(u[4], u[5], u[6], u[7]);
}

// ---------------- fused prep: feat (MLP-2) blocks + B-repack/bias blocks -----
__global__ void prep_kernel(const float* __restrict__ x,
                            const float* __restrict__ coeffs) {
    if (blockIdx.x < FEAT_BLOCKS) {
        // 2 independent float4 per thread: (n, jl) and (n, jl+256); both loads
        // hoisted -> MLP=2 on the DRAM-bound path.
        const int idx = blockIdx.x * 256 + threadIdx.x;    // over N*I/8
        const int n  = idx >> 8;           // 256 thread-slots per row
        const int jl = idx & 255;
        const float4* xr = reinterpret_cast<const float4*>(x) + (size_t)n * 512;
        float4 xv0 = xr[jl];
        float4 xv1 = xr[jl + 256];
        feat_store4(n, jl,       xv0);
        feat_store4(n, jl + 256, xv1);
    } else {
        // repack B (d=1..4 -> fp16 swizzled) + bias[o] = sum_i c[o,i,0]
        const int o = blockIdx.x - FEAT_BLOCKS;
        float bsum = 0.0f;
        for (int t = 0; t < I_DIM / 256; ++t) {
            int i = t * 256 + threadIdx.x;
            const float* c5 = coeffs + ((size_t)o * I_DIM + i) * 5;
            float c0 = c5[0];
            __half2 p01 = __floats2half2_rn(c5[1], c5[2]);
            __half2 p23 = __floats2half2_rn(c5[3], c5[4]);
            uint2 u = make_uint2(*reinterpret_cast<uint32_t*>(&p01),
                                 *reinterpret_cast<uint32_t*>(&p23));
            uint32_t off = (uint32_t)(o & 127) * 128u + (uint32_t)(i & 15) * 8u;
            size_t base  = ((size_t)((o >> 7) * NPAIR + (i >> 4))) << 14;
            *reinterpret_cast<uint2*>(g_B + base + swz128(off)) = u;
            bsum += c0;
        }
        __shared__ float red[256];
        red[threadIdx.x] = bsum;
        __syncthreads();
        for (int off = 128; off > 0; off >>= 1) {
            if (threadIdx.x < off) red[threadIdx.x] += red[threadIdx.x + off];
            __syncthreads();
        }
        if (threadIdx.x == 0) g_bias[o] = red[0];
    }
}

// ---------------- GEMM: 128x128 CTA tile, 8 warps (4m x 2n), mma.sync -------
__global__ void __launch_bounds__(256, 2)
gemm_kernel(float* __restrict__ C) {
    extern __shared__ __align__(1024) unsigned char smem[];
    const uint32_t sb = smem_u32(smem);
    const uint32_t stage0 = sb + 1024;

    const int tid  = threadIdx.x;
    const int wid  = tid >> 5, lane = tid & 31;
    const int wm   = wid & 3;          // 0..3 -> 32-row slice of M tile
    const int wn   = wid >> 2;         // 0..1 -> 64-col slice of N tile
    const int mtile = blockIdx.y, ntile = blockIdx.x;

    if (tid == 0) {
#pragma unroll
        for (int s = 0; s < NSTG; ++s) mbar_init(sb + s * 8, 1);
    }
    __syncthreads();

    const unsigned char* aSrc = g_A + ((size_t)mtile * NPAIR << 14);
    const unsigned char* bSrc = g_B + ((size_t)ntile * NPAIR << 14);

    if (tid == 0) {
#pragma unroll
        for (int p = 0; p < NSTG; ++p) {
            uint32_t fb = sb + p * 8;
            uint32_t dst = stage0 + p * STG_B;
            mbar_expect_tx(fb, STG_B);
            bulk_g2s(dst,          aSrc + ((size_t)p << 14), TILE_B, fb);
            bulk_g2s(dst + TILE_B, bSrc + ((size_t)p << 14), TILE_B, fb);
        }
    }

    float acc[2][8][4];
#pragma unroll
    for (int mi = 0; mi < 2; ++mi)
#pragma unroll
        for (int ni = 0; ni < 8; ++ni)
#pragma unroll
            for (int r = 0; r < 4; ++r) acc[mi][ni][r] = 0.0f;

    const int g = lane >> 3, r8 = lane & 7;
    const uint32_t aRow = (uint32_t)(wm * 32 + ((g & 1) << 3) + r8);
    const uint32_t bRow = (uint32_t)(wn * 64 + ((g >> 1) << 3) + r8);
    const uint32_t aKb  = (uint32_t)((g >> 1) << 4);
    const uint32_t bKb  = (uint32_t)((g & 1) << 4);

    for (int k = 0; k < NPAIR; ++k) {
        const int sp = k % NSTG;
        const uint32_t fb = sb + sp * 8;
        mbar_wait(fb, (uint32_t)((k / NSTG) & 1));

        const uint32_t stA = stage0 + sp * STG_B;
        const uint32_t stB = stA + TILE_B;

#pragma unroll
        for (int ks = 0; ks < 4; ++ks) {
            uint32_t a[2][4];
#pragma unroll
            for (int mi = 0; mi < 2; ++mi) {
                uint32_t off = (aRow + mi * 16) * 128u + (uint32_t)(ks * 32) + aKb;
                ldsm_x4(a[mi][0], a[mi][1], a[mi][2], a[mi][3], stA + swz128(off));
            }
            uint32_t b[4][4];
#pragma unroll
            for (int nj = 0; nj < 4; ++nj) {
                uint32_t off = (bRow + nj * 16) * 128u + (uint32_t)(ks * 32) + bKb;
                ldsm_x4(b[nj][0], b[nj][1], b[nj][2], b[nj][3], stB + swz128(off));
            }
#pragma unroll
            for (int mi = 0; mi < 2; ++mi)
#pragma unroll
                for (int ni = 0; ni < 8; ++ni)
                    mma16816(acc[mi][ni], a[mi],
                             b[ni >> 1][(ni & 1) * 2], b[ni >> 1][(ni & 1) * 2 + 1]);
        }

        __syncthreads();   // all warps done reading stage sp
        if (tid == 0 && k + NSTG < NPAIR) {
            const int kn = k + NSTG;
            uint32_t dst = stage0 + sp * STG_B;
            mbar_expect_tx(fb, STG_B);
            bulk_g2s(dst,          aSrc + ((size_t)kn << 14), TILE_B, fb);
            bulk_g2s(dst + TILE_B, bSrc + ((size_t)kn << 14), TILE_B, fb);
        }
    }

    // ---------------- epilogue: bias + clamp, float2 stores ------------------
    const int mBase = mtile * MT + wm * 32 + (lane >> 2);
    const int nBase = ntile * NT + wn * 64 + (lane & 3) * 2;

#pragma unroll
    for (int mi = 0; mi < 2; ++mi) {
#pragma unroll
        for (int ni = 0; ni < 8; ++ni) {
            const int n = nBase + ni * 8;
            const float b0 = g_bias[n], b1 = g_bias[n + 1];
            const int m0 = mBase + mi * 16;
            float2 v0, v1;
            v0.x = clampf(acc[mi][ni][0] + b0);
            v0.y = clampf(acc[mi][ni][1] + b1);
            v1.x = clampf(acc[mi][ni][2] + b0);
            v1.y = clampf(acc[mi][ni][3] + b1);
            *reinterpret_cast<float2*>(C + (size_t)m0 * O_DIM + n)       = v0;
            *reinterpret_cast<float2*>(C + (size_t)(m0 + 8) * O_DIM + n) = v1;
        }
    }
}

// ---------------------------------------------------------------------------
extern "C" void kernel_launch(void* const* d_in, const int* in_sizes, int n_in,
                              void* d_out, int out_size) {
    const float* x      = (const float*)d_in[0];
    const float* coeffs = (const float*)d_in[1];
    float* out          = (float*)d_out;

    cudaFuncSetAttribute(gemm_kernel, cudaFuncAttributeMaxDynamicSharedMemorySize, SMEM_TOTAL);

    prep_kernel<<<FEAT_BLOCKS + O_DIM, 256>>>(x, coeffs);
    gemm_kernel<<<dim3(O_DIM / NT, N_ROWS / MT), 256, SMEM_TOTAL>>>(out);
}

// round 14
// speedup vs baseline: 1.3282x; 1.0168x over previous
#include <cuda_runtime.h>
#include <cuda_fp16.h>
#include <cstdint>

// ---------------------------------------------------------------------------
// ChebyKAN: out[n,o] = clip( sum_{i,d=0..4} T_d(tanh(clip(x[n,i]))) * coeffs[o,i,d] )
// N=16384, I=2048, O=2048.  T0==1 folded into bias; GEMM K = I*4 = 8192, fp16.
// ldmatrix + mma.sync.m16n8k16 (compute_103 baseline ISA; tcgen05 unavailable).
// R8 base; mainloop consumes TWO k-chunks per __syncthreads/refill round
// (64 sync rounds instead of 128; same 3-stage ring, same hazard guarantees).
// ---------------------------------------------------------------------------

#define N_ROWS 16384
#define I_DIM  2048
#define O_DIM  2048
#define KDIM   8192
#define MT     128
#define NT     128
#define NPAIR  (KDIM / 64)           // 128 k-chunks of KC=64
#define NSTG   3
#define TILE_B 16384                 // 128 rows x 128 B (64 fp16)
#define STG_B  (2 * TILE_B)
#define SMEM_TOTAL (1024 + NSTG * STG_B)   // 99328
#define FEAT_BLOCKS (N_ROWS * I_DIM / 4 / 256)   // 32768
#define CLAMP10 10.0f

__device__ __align__(1024) unsigned char g_A[(size_t)N_ROWS * KDIM * 2]; // 256 MB
__device__ __align__(1024) unsigned char g_B[(size_t)O_DIM  * KDIM * 2]; //  32 MB
__device__ float g_bias[O_DIM];

static __device__ __forceinline__ uint32_t swz128(uint32_t off) {
    return off ^ ((off >> 3) & 0x70);
}
static __device__ __forceinline__ float clampf(float v) {
    return fminf(fmaxf(v, -CLAMP10), CLAMP10);
}
static __device__ __forceinline__ uint32_t smem_u32(const void* p) {
    return (uint32_t)__cvta_generic_to_shared(p);
}
static __device__ __forceinline__ void mbar_init(uint32_t a, uint32_t cnt) {
    asm volatile("mbarrier.init.shared.b64 [%0], %1;" :: "r"(a), "r"(cnt) : "memory");
}
static __device__ __forceinline__ void mbar_expect_tx(uint32_t a, uint32_t bytes) {
    asm volatile("mbarrier.arrive.expect_tx.shared.b64 _, [%0], %1;" :: "r"(a), "r"(bytes) : "memory");
}
static __device__ __forceinline__ void mbar_wait(uint32_t a, uint32_t parity) {
    asm volatile(
        "{\n\t.reg .pred P;\n\t"
        "WL_%=:\n\t"
        "mbarrier.try_wait.parity.acquire.cta.shared::cta.b64 P, [%0], %1, 0x989680;\n\t"
        "@P bra.uni WD_%=;\n\t"
        "bra.uni WL_%=;\n\t"
        "WD_%=:\n\t}"
        :: "r"(a), "r"(parity) : "memory");
}
static __device__ __forceinline__ void bulk_g2s(uint32_t dst, const void* src,
                                                uint32_t bytes, uint32_t mbar) {
    asm volatile(
        "cp.async.bulk.shared::cluster.global.mbarrier::complete_tx::bytes [%0], [%1], %2, [%3];"
        :: "r"(dst), "l"(src), "r"(bytes), "r"(mbar) : "memory");
}
static __device__ __forceinline__ void ldsm_x4(uint32_t& r0, uint32_t& r1,
                                               uint32_t& r2, uint32_t& r3, uint32_t a) {
    asm volatile("ldmatrix.sync.aligned.m8n8.x4.shared.b16 {%0,%1,%2,%3}, [%4];"
                 : "=r"(r0), "=r"(r1), "=r"(r2), "=r"(r3) : "r"(a));
}
static __device__ __forceinline__ void mma16816(float* d, const uint32_t* a,
                                                uint32_t b0, uint32_t b1) {
    asm volatile(
        "mma.sync.aligned.m16n8k16.row.col.f32.f16.f16.f32 "
        "{%0,%1,%2,%3}, {%4,%5,%6,%7}, {%8,%9}, {%0,%1,%2,%3};"
        : "+f"(d[0]), "+f"(d[1]), "+f"(d[2]), "+f"(d[3])
        : "r"(a[0]), "r"(a[1]), "r"(a[2]), "r"(a[3]), "r"(b0), "r"(b1));
}
static __device__ __forceinline__ float tanh_fast(float v) {
    float r;
    asm("tanh.approx.f32 %0, %1;" : "=f"(r) : "f"(v));
    return r;
}

// ---------------- fused prep: feature map blocks + B-repack/bias blocks ------
__global__ void prep_kernel(const float* __restrict__ x,
                            const float* __restrict__ coeffs) {
    if (blockIdx.x < FEAT_BLOCKS) {
        const int idx4 = blockIdx.x * 256 + threadIdx.x;     // over N*I/4
        const int n = idx4 >> 9;
        const int j = idx4 & 511;
        float4 xv = reinterpret_cast<const float4*>(x)[idx4];
        float vv[4] = {xv.x, xv.y, xv.z, xv.w};
        uint32_t u[8];
#pragma unroll
        for (int q = 0; q < 4; ++q) {
            float t  = tanh_fast(clampf(vv[q]));
            float t2 = 2.0f * t * t  - 1.0f;
            float t3 = 2.0f * t * t2 - t;
            float t4 = 2.0f * t * t3 - t2;
            __half2 p01 = __floats2half2_rn(t,  t2);
            __half2 p23 = __floats2half2_rn(t3, t4);
            u[q * 2 + 0] = *reinterpret_cast<uint32_t*>(&p01);
            u[q * 2 + 1] = *reinterpret_cast<uint32_t*>(&p23);
        }
        const int i0 = j * 4;
        const uint32_t off0 = (uint32_t)(n & 127) * 128u + (uint32_t)(i0 & 15) * 8u;
        const size_t  base  = ((size_t)((n >> 7) * NPAIR + (i0 >> 4))) << 14;
        *reinterpret_cast<uint4*>(g_A + base + swz128(off0)) =
            make_uint4(u[0], u[1], u[2], u[3]);
        *reinterpret_cast<uint4*>(g_A + base + swz128(off0 + 16)) =
            make_uint4(u[4], u[5], u[6], u[7]);
    } else {
        const int o = blockIdx.x - FEAT_BLOCKS;
        float bsum = 0.0f;
        for (int t = 0; t < I_DIM / 256; ++t) {
            int i = t * 256 + threadIdx.x;
            const float* c5 = coeffs + ((size_t)o * I_DIM + i) * 5;
            float c0 = c5[0];
            __half2 p01 = __floats2half2_rn(c5[1], c5[2]);
            __half2 p23 = __floats2half2_rn(c5[3], c5[4]);
            uint2 u = make_uint2(*reinterpret_cast<uint32_t*>(&p01),
                                 *reinterpret_cast<uint32_t*>(&p23));
            uint32_t off = (uint32_t)(o & 127) * 128u + (uint32_t)(i & 15) * 8u;
            size_t base  = ((size_t)((o >> 7) * NPAIR + (i >> 4))) << 14;
            *reinterpret_cast<uint2*>(g_B + base + swz128(off)) = u;
            bsum += c0;
        }
        __shared__ float red[256];
        red[threadIdx.x] = bsum;
        __syncthreads();
        for (int off = 128; off > 0; off >>= 1) {
            if (threadIdx.x < off) red[threadIdx.x] += red[threadIdx.x + off];
            __syncthreads();
        }
        if (threadIdx.x == 0) g_bias[o] = red[0];
    }
}

// ---------------- GEMM: 128x128 CTA tile, 8 warps, 2 chunks per sync ---------
__global__ void __launch_bounds__(256, 2)
gemm_kernel(float* __restrict__ C) {
    extern __shared__ __align__(1024) unsigned char smem[];
    const uint32_t sb = smem_u32(smem);
    const uint32_t stage0 = sb + 1024;

    const int tid  = threadIdx.x;
    const int wid  = tid >> 5, lane = tid & 31;
    const int wm   = wid & 3;
    const int wn   = wid >> 2;
    const int mtile = blockIdx.y, ntile = blockIdx.x;

    if (tid == 0) {
#pragma unroll
        for (int s = 0; s < NSTG; ++s) mbar_init(sb + s * 8, 1);
    }
    __syncthreads();

    const unsigned char* aSrc = g_A + ((size_t)mtile * NPAIR << 14);
    const unsigned char* bSrc = g_B + ((size_t)ntile * NPAIR << 14);

    if (tid == 0) {
#pragma unroll
        for (int p = 0; p < NSTG; ++p) {
            uint32_t fb = sb + p * 8;
            uint32_t dst = stage0 + p * STG_B;
            mbar_expect_tx(fb, STG_B);
            bulk_g2s(dst,          aSrc + ((size_t)p << 14), TILE_B, fb);
            bulk_g2s(dst + TILE_B, bSrc + ((size_t)p << 14), TILE_B, fb);
        }
    }

    float acc[2][8][4];
#pragma unroll
    for (int mi = 0; mi < 2; ++mi)
#pragma unroll
        for (int ni = 0; ni < 8; ++ni)
#pragma unroll
            for (int r = 0; r < 4; ++r) acc[mi][ni][r] = 0.0f;

    const int g = lane >> 3, r8 = lane & 7;
    const uint32_t aRow = (uint32_t)(wm * 32 + ((g & 1) << 3) + r8);
    const uint32_t bRow = (uint32_t)(wn * 64 + ((g >> 1) << 3) + r8);
    const uint32_t aKb  = (uint32_t)((g >> 1) << 4);
    const uint32_t bKb  = (uint32_t)((g & 1) << 4);

    for (int k = 0; k < NPAIR; k += 2) {
        // ---- consume chunks k and k+1 (no sync in between) ----
#pragma unroll
        for (int c = 0; c < 2; ++c) {
            const int kc = k + c;
            const int sp = kc % NSTG;
            const uint32_t fb = sb + sp * 8;
            mbar_wait(fb, (uint32_t)((kc / NSTG) & 1));

            const uint32_t stA = stage0 + sp * STG_B;
            const uint32_t stB = stA + TILE_B;

#pragma unroll
            for (int ks = 0; ks < 4; ++ks) {
                uint32_t a[2][4];
#pragma unroll
                for (int mi = 0; mi < 2; ++mi) {
                    uint32_t off = (aRow + mi * 16) * 128u + (uint32_t)(ks * 32) + aKb;
                    ldsm_x4(a[mi][0], a[mi][1], a[mi][2], a[mi][3], stA + swz128(off));
                }
                uint32_t b[4][4];
#pragma unroll
                for (int nj = 0; nj < 4; ++nj) {
                    uint32_t off = (bRow + nj * 16) * 128u + (uint32_t)(ks * 32) + bKb;
                    ldsm_x4(b[nj][0], b[nj][1], b[nj][2], b[nj][3], stB + swz128(off));
                }
#pragma unroll
                for (int mi = 0; mi < 2; ++mi)
#pragma unroll
                    for (int ni = 0; ni < 8; ++ni)
                        mma16816(acc[mi][ni], a[mi],
                                 b[ni >> 1][(ni & 1) * 2], b[ni >> 1][(ni & 1) * 2 + 1]);
            }
        }

        __syncthreads();   // all warps done reading stages k%3 and (k+1)%3
        if (tid == 0) {
#pragma unroll
            for (int c = 0; c < 2; ++c) {
                const int kn = k + c + NSTG;
                if (kn < NPAIR) {
                    const int sp = kn % NSTG;      // == (k+c)%3
                    const uint32_t fb = sb + sp * 8;
                    uint32_t dst = stage0 + sp * STG_B;
                    mbar_expect_tx(fb, STG_B);
                    bulk_g2s(dst,          aSrc + ((size_t)kn << 14), TILE_B, fb);
                    bulk_g2s(dst + TILE_B, bSrc + ((size_t)kn << 14), TILE_B, fb);
                }
            }
        }
    }

    // ---------------- epilogue: bias + clamp, float2 stores ------------------
    const int mBase = mtile * MT + wm * 32 + (lane >> 2);
    const int nBase = ntile * NT + wn * 64 + (lane & 3) * 2;

#pragma unroll
    for (int mi = 0; mi < 2; ++mi) {
#pragma unroll
        for (int ni = 0; ni < 8; ++ni) {
            const int n = nBase + ni * 8;
            const float b0 = g_bias[n], b1 = g_bias[n + 1];
            const int m0 = mBase + mi * 16;
            float2 v0, v1;
            v0.x = clampf(acc[mi][ni][0] + b0);
            v0.y = clampf(acc[mi][ni][1] + b1);
            v1.x = clampf(acc[mi][ni][2] + b0);
            v1.y = clampf(acc[mi][ni][3] + b1);
            *reinterpret_cast<float2*>(C + (size_t)m0 * O_DIM + n)       = v0;
            *reinterpret_cast<float2*>(C + (size_t)(m0 + 8) * O_DIM + n) = v1;
        }
    }
}

// ---------------------------------------------------------------------------
extern "C" void kernel_launch(void* const* d_in, const int* in_sizes, int n_in,
                              void* d_out, int out_size) {
    const float* x      = (const float*)d_in[0];
    const float* coeffs = (const float*)d_in[1];
    float* out          = (float*)d_out;

    cudaFuncSetAttribute(gemm_kernel, cudaFuncAttributeMaxDynamicSharedMemorySize, SMEM_TOTAL);

    prep_kernel<<<FEAT_BLOCKS + O_DIM, 256>>>(x, coeffs);
    gemm_kernel<<<dim3(O_DIM / NT, N_ROWS / MT), 256, SMEM_TOTAL>>>(out);
}